// round 4
// baseline (speedup 1.0000x reference)
#include <cuda_runtime.h>
#include <cstdint>

#define NTOK   8192              // B*S
#define T_SLOT 16
#define E_DIM  1024              // token embedding floats (4096 B)
#define D_DIM  100               // entity embedding floats (400 B)
#define OUT_W  (E_DIM + D_DIM)   // 1124 floats
#define WPB    8                 // warps per block

__global__ __launch_bounds__(32 * WPB, 5)
void fuse_triples_dual_kernel(const int*   __restrict__ inputs,   // [NTOK]
                              const int*   __restrict__ triples,  // [NTOK,T,3]
                              const int*   __restrict__ flags,    // [NTOK,T]
                              const float* __restrict__ emb,      // [VOCAB,1024]
                              const float* __restrict__ ent,      // [ENT_VOCAB,100]
                              float*       __restrict__ out)      // [NTOK,1124]
{
    __shared__ alignas(128) float              buf[WPB][E_DIM];   // 4 KB/warp
    __shared__ alignas(8)   unsigned long long mbar[WPB];

    const int w    = threadIdx.x >> 5;
    const int lane = threadIdx.x & 31;
    const int tokA = (blockIdx.x * WPB + w) * 2;   // TMA-copied token
    const int tokB = tokA + 1;                     // LDG/STG-copied token

    const uint32_t buf_addr  = (uint32_t)__cvta_generic_to_shared(&buf[w][0]);
    const uint32_t mbar_addr = (uint32_t)__cvta_generic_to_shared(&mbar[w]);

    const int vrowA = inputs[tokA];
    const int vrowB = inputs[tokB];

    // ---- TMA load of token A's 4KB embedding row ----
    if (lane == 0) {
        asm volatile("mbarrier.init.shared::cta.b64 [%0], 1;"
                     :: "r"(mbar_addr) : "memory");
    }
    __syncwarp();
    if (lane == 0) {
        asm volatile("mbarrier.arrive.expect_tx.shared::cta.b64 _, [%0], %1;"
                     :: "r"(mbar_addr), "r"(4096u) : "memory");
        asm volatile("cp.async.bulk.shared::cta.global.mbarrier::complete_tx::bytes"
                     " [%0], [%1], %2, [%3];"
                     :: "r"(buf_addr),
                        "l"(emb + (size_t)vrowA * E_DIM),
                        "r"(4096u), "r"(mbar_addr) : "memory");
    }

    // ---- token B copy: first half loads issued early (LSU path) ----
    const float4* __restrict__ srcB =
        reinterpret_cast<const float4*>(emb + (size_t)vrowB * E_DIM);
    float4* __restrict__ dstB =
        reinterpret_cast<float4*>(out + (size_t)tokB * OUT_W);
    float4 c0 = srcB[lane];
    float4 c1 = srcB[lane + 32];
    float4 c2 = srcB[lane + 64];
    float4 c3 = srcB[lane + 96];

    // ---- decode triple slots for BOTH tokens: lanes 0..15 -> A, 16..31 -> B
    const int mytok  = (lane < 16) ? tokA : tokB;
    const int myslot = lane & 15;
    int e = -1;
    {
        const int f = flags[mytok * T_SLOT + myslot];
        if (f == 1)      e = triples[(mytok * T_SLOT + myslot) * 3 + 1]; // tail
        else if (f == 2) e = triples[(mytok * T_SLOT + myslot) * 3 + 0]; // head
    }
    const unsigned vmask = __ballot_sync(0xffffffffu, e >= 0);
    const int cntA = __popc(vmask & 0xFFFFu);
    const int cntB = __popc(vmask >> 16);

    // ---- gathers for both tokens (32 independent LDG.128 per lane<25) ----
    float4 accA = make_float4(0.f, 0.f, 0.f, 0.f);
    float4 accB = make_float4(0.f, 0.f, 0.f, 0.f);
    #pragma unroll
    for (int j = 0; j < T_SLOT; ++j) {
        const int ejA = __shfl_sync(0xffffffffu, e, j);
        const int ejB = __shfl_sync(0xffffffffu, e, j + 16);
        if (lane < 25) {
            if (ejA >= 0) {
                const float4 r = reinterpret_cast<const float4*>(
                                     ent + (size_t)ejA * D_DIM)[lane];
                accA.x += r.x; accA.y += r.y; accA.z += r.z; accA.w += r.w;
            }
            if (ejB >= 0) {
                const float4 r = reinterpret_cast<const float4*>(
                                     ent + (size_t)ejB * D_DIM)[lane];
                accB.x += r.x; accB.y += r.y; accB.z += r.z; accB.w += r.w;
            }
        }
    }

    // ---- token B copy: store first half, load+store second half ----
    dstB[lane]      = c0;
    dstB[lane + 32] = c1;
    dstB[lane + 64] = c2;
    dstB[lane + 96] = c3;
    c0 = srcB[lane + 128];
    c1 = srcB[lane + 160];
    c2 = srcB[lane + 192];
    c3 = srcB[lane + 224];

    // ---- averaged entity parts ----
    if (lane < 25) {
        const float invA = 1.0f / (float)(cntA > 0 ? cntA : 1);
        const float invB = 1.0f / (float)(cntB > 0 ? cntB : 1);
        accA.x *= invA; accA.y *= invA; accA.z *= invA; accA.w *= invA;
        accB.x *= invB; accB.y *= invB; accB.z *= invB; accB.w *= invB;
        reinterpret_cast<float4*>(out + (size_t)tokA * OUT_W + E_DIM)[lane] = accA;
        reinterpret_cast<float4*>(out + (size_t)tokB * OUT_W + E_DIM)[lane] = accB;
    }

    dstB[lane + 128] = c0;
    dstB[lane + 160] = c1;
    dstB[lane + 192] = c2;
    dstB[lane + 224] = c3;

    // ---- drain TMA load of A, then TMA store A's row out ----
    if (lane == 0) {
        uint32_t done = 0;
        while (!done) {
            asm volatile(
                "{ .reg .pred p;\n\t"
                "  mbarrier.try_wait.parity.shared::cta.b64 p, [%1], 0, 0x989680;\n\t"
                "  selp.b32 %0, 1, 0, p; }"
                : "=r"(done) : "r"(mbar_addr) : "memory");
        }
        asm volatile("cp.async.bulk.global.shared::cta.bulk_group [%0], [%1], %2;"
                     :: "l"(out + (size_t)tokA * OUT_W),
                        "r"(buf_addr), "r"(4096u) : "memory");
        asm volatile("cp.async.bulk.commit_group;" ::: "memory");
        asm volatile("cp.async.bulk.wait_group 0;" ::: "memory");
    }
}

extern "C" void kernel_launch(void* const* d_in, const int* in_sizes, int n_in,
                              void* d_out, int out_size)
{
    const int*   inputs  = (const int*)  d_in[0];
    const int*   triples = (const int*)  d_in[1];
    const int*   flags   = (const int*)  d_in[2];
    const float* emb     = (const float*)d_in[3];
    const float* ent     = (const float*)d_in[4];
    float*       out     = (float*)      d_out;

    // 2 tokens per warp: 4096 warps = 512 blocks * 8 warps
    fuse_triples_dual_kernel<<<NTOK / (2 * WPB), 32 * WPB>>>(inputs, triples,
                                                             flags, emb, ent, out);
}

// round 5
// speedup vs baseline: 1.0843x; 1.0843x over previous
#include <cuda_runtime.h>
#include <cstdint>

#define NTOK    8192             // B*S
#define T_SLOT  16
#define E_DIM   1024             // token embedding floats (4096 B)
#define D_DIM   100              // entity embedding floats (400 B)
#define OUT_W   (E_DIM + D_DIM)  // 1124 floats (4496 B)

#define NCOPY       256          // copy blocks
#define ROWS_PER_CB 32           // 256*32 = 8192 rows
#define DEPTH       8            // smem ring slots (4 KB each)
#define LOOKAHEAD   4            // loads issued ahead of store pointer
#define GW          8            // gather warps per block

__global__ __launch_bounds__(256)
void fuse_triples_split_kernel(const int*   __restrict__ inputs,   // [NTOK]
                               const int*   __restrict__ triples,  // [NTOK,T,3]
                               const int*   __restrict__ flags,    // [NTOK,T]
                               const float* __restrict__ emb,      // [VOCAB,1024]
                               const float* __restrict__ ent,      // [ENT_VOCAB,100]
                               float*       __restrict__ out)      // [NTOK,1124]
{
    if (blockIdx.x < NCOPY) {
        // ================= COPY ROLE: deep TMA load/store pipeline ========
        __shared__ alignas(128) float              ring[DEPTH][E_DIM]; // 32 KB
        __shared__ alignas(8)   unsigned long long mbar[DEPTH];

        if (threadIdx.x != 0) return;   // single orchestrator thread

        const int base = blockIdx.x * ROWS_PER_CB;

        #pragma unroll
        for (int s = 0; s < DEPTH; ++s) {
            const uint32_t mb = (uint32_t)__cvta_generic_to_shared(&mbar[s]);
            asm volatile("mbarrier.init.shared::cta.b64 [%0], 1;"
                         :: "r"(mb) : "memory");
        }
        asm volatile("fence.proxy.async.shared::cta;" ::: "memory");

        // prologue: issue LOOKAHEAD loads
        #pragma unroll
        for (int i = 0; i < LOOKAHEAD; ++i) {
            const uint32_t mb  = (uint32_t)__cvta_generic_to_shared(&mbar[i]);
            const uint32_t dst = (uint32_t)__cvta_generic_to_shared(&ring[i][0]);
            const int vrow = inputs[base + i];
            asm volatile("mbarrier.arrive.expect_tx.shared::cta.b64 _, [%0], %1;"
                         :: "r"(mb), "r"(4096u) : "memory");
            asm volatile("cp.async.bulk.shared::cta.global.mbarrier::complete_tx::bytes"
                         " [%0], [%1], %2, [%3];"
                         :: "r"(dst), "l"(emb + (size_t)vrow * E_DIM),
                            "r"(4096u), "r"(mb) : "memory");
        }

        for (int i = 0; i < ROWS_PER_CB; ++i) {
            const int      slot  = i & (DEPTH - 1);
            const uint32_t phase = (uint32_t)((i >> 3) & 1);
            const uint32_t mb  = (uint32_t)__cvta_generic_to_shared(&mbar[slot]);
            const uint32_t buf = (uint32_t)__cvta_generic_to_shared(&ring[slot][0]);

            // wait for load of row i
            uint32_t done = 0;
            while (!done) {
                asm volatile(
                    "{ .reg .pred p;\n\t"
                    "  mbarrier.try_wait.parity.shared::cta.b64 p, [%1], %2, 0x989680;\n\t"
                    "  selp.b32 %0, 1, 0, p; }"
                    : "=r"(done) : "r"(mb), "r"(phase) : "memory");
            }

            // store row i: smem -> out (first 4096 B of the output row)
            asm volatile("cp.async.bulk.global.shared::cta.bulk_group [%0], [%1], %2;"
                         :: "l"(out + (size_t)(base + i) * OUT_W),
                            "r"(buf), "r"(4096u) : "memory");
            asm volatile("cp.async.bulk.commit_group;" ::: "memory");

            const int nxt = i + LOOKAHEAD;
            if (nxt < ROWS_PER_CB) {
                // allow at most LOOKAHEAD-1 outstanding stores => the store
                // that used slot (nxt & 7) (row nxt-DEPTH = i-4) has drained
                asm volatile("cp.async.bulk.wait_group %0;"
                             :: "n"(LOOKAHEAD - 1) : "memory");
                const int      ns  = nxt & (DEPTH - 1);
                const uint32_t nmb = (uint32_t)__cvta_generic_to_shared(&mbar[ns]);
                const uint32_t nds = (uint32_t)__cvta_generic_to_shared(&ring[ns][0]);
                const int vrow = inputs[base + nxt];
                asm volatile("mbarrier.arrive.expect_tx.shared::cta.b64 _, [%0], %1;"
                             :: "r"(nmb), "r"(4096u) : "memory");
                asm volatile("cp.async.bulk.shared::cta.global.mbarrier::complete_tx::bytes"
                             " [%0], [%1], %2, [%3];"
                             :: "r"(nds), "l"(emb + (size_t)vrow * E_DIM),
                                "r"(4096u), "r"(nmb) : "memory");
            }
        }
        asm volatile("cp.async.bulk.wait_group 0;" ::: "memory");
        return;
    }

    // ================= GATHER ROLE: warp per token (entity part only) =====
    const int gwarp = ((blockIdx.x - NCOPY) * blockDim.x + threadIdx.x) >> 5;
    const int lane  = threadIdx.x & 31;
    const int token = gwarp;
    if (token >= NTOK) return;

    int e = -1;
    if (lane < T_SLOT) {
        const int f = flags[token * T_SLOT + lane];
        if (f == 1)      e = triples[(token * T_SLOT + lane) * 3 + 1]; // tail
        else if (f == 2) e = triples[(token * T_SLOT + lane) * 3 + 0]; // head
    }
    const unsigned vmask = __ballot_sync(0xffffffffu, e >= 0);
    const int cnt = __popc(vmask & 0xFFFFu);

    float4 acc = make_float4(0.f, 0.f, 0.f, 0.f);
    #pragma unroll
    for (int j = 0; j < T_SLOT; ++j) {
        const int ej = __shfl_sync(0xffffffffu, e, j);
        if (ej >= 0 && lane < 25) {
            const float4 r = reinterpret_cast<const float4*>(
                                 ent + (size_t)ej * D_DIM)[lane];
            acc.x += r.x; acc.y += r.y; acc.z += r.z; acc.w += r.w;
        }
    }
    if (lane < 25) {
        const float inv = 1.0f / (float)(cnt > 0 ? cnt : 1);
        acc.x *= inv; acc.y *= inv; acc.z *= inv; acc.w *= inv;
        reinterpret_cast<float4*>(out + (size_t)token * OUT_W + E_DIM)[lane] = acc;
    }
}

extern "C" void kernel_launch(void* const* d_in, const int* in_sizes, int n_in,
                              void* d_out, int out_size)
{
    const int*   inputs  = (const int*)  d_in[0];
    const int*   triples = (const int*)  d_in[1];
    const int*   flags   = (const int*)  d_in[2];
    const float* emb     = (const float*)d_in[3];
    const float* ent     = (const float*)d_in[4];
    float*       out     = (float*)      d_out;

    const int gather_blocks = NTOK / GW;            // 1024
    fuse_triples_split_kernel<<<NCOPY + gather_blocks, 32 * GW>>>(
        inputs, triples, flags, emb, ent, out);
}

// round 6
// speedup vs baseline: 1.0992x; 1.0137x over previous
#include <cuda_runtime.h>
#include <cstdint>

#define NTOK   8192              // B*S
#define T_SLOT 16
#define E_DIM  1024              // token embedding floats (4096 B)
#define D_DIM  100               // entity embedding floats (400 B)
#define OUT_W  (E_DIM + D_DIM)   // 1124 floats
#define WPB    4                 // warps (tokens) per block

__global__ __launch_bounds__(32 * WPB)
void fuse_triples_bulk_kernel(const int*   __restrict__ inputs,   // [NTOK]
                              const int*   __restrict__ triples,  // [NTOK,T,3]
                              const int*   __restrict__ flags,    // [NTOK,T]
                              const float* __restrict__ emb,      // [VOCAB,1024]
                              const float* __restrict__ ent,      // [ENT_VOCAB,100]
                              float*       __restrict__ out)      // [NTOK,1124]
{
    // per-warp smem: 4KB token row + 16 x 400B entity slots
    __shared__ alignas(128) float              tokb[WPB][E_DIM];          // 16 KB
    __shared__ alignas(16)  float              entb[WPB][T_SLOT][D_DIM];  // 25.6 KB
    __shared__ alignas(8)   unsigned long long mbar[WPB];

    const int w     = threadIdx.x >> 5;
    const int lane  = threadIdx.x & 31;
    const int token = blockIdx.x * WPB + w;

    const uint32_t mb = (uint32_t)__cvta_generic_to_shared(&mbar[w]);

    // ---- decode triple slots (lanes 0..15) — only LDG traffic left ----
    int e = -1;
    if (lane < T_SLOT) {
        const int f = flags[token * T_SLOT + lane];
        if (f == 1)      e = triples[(token * T_SLOT + lane) * 3 + 1]; // tail
        else if (f == 2) e = triples[(token * T_SLOT + lane) * 3 + 0]; // head
    }
    const unsigned vmask = __ballot_sync(0xffffffffu, e >= 0);
    const int cnt = __popc(vmask & 0xFFFFu);

    const int vrow = inputs[token];

    // ---- mbarrier init (lane 0), make visible to async proxy ----
    if (lane == 0) {
        asm volatile("mbarrier.init.shared::cta.b64 [%0], 1;"
                     :: "r"(mb) : "memory");
        asm volatile("fence.proxy.async.shared::cta;" ::: "memory");
    }
    __syncwarp();

    // ---- lane 0 issues ALL bulk loads against one barrier ----
    if (lane == 0) {
        const uint32_t total = 4096u + (uint32_t)cnt * 400u;
        asm volatile("mbarrier.arrive.expect_tx.shared::cta.b64 _, [%0], %1;"
                     :: "r"(mb), "r"(total) : "memory");
        const uint32_t tdst = (uint32_t)__cvta_generic_to_shared(&tokb[w][0]);
        asm volatile("cp.async.bulk.shared::cta.global.mbarrier::complete_tx::bytes"
                     " [%0], [%1], %2, [%3];"
                     :: "r"(tdst), "l"(emb + (size_t)vrow * E_DIM),
                        "r"(4096u), "r"(mb) : "memory");
    }
    #pragma unroll
    for (int j = 0; j < T_SLOT; ++j) {
        const int ej = __shfl_sync(0xffffffffu, e, j);   // warp-collective
        if (lane == 0 && ej >= 0) {
            const uint32_t edst = (uint32_t)__cvta_generic_to_shared(&entb[w][j][0]);
            asm volatile("cp.async.bulk.shared::cta.global.mbarrier::complete_tx::bytes"
                         " [%0], [%1], %2, [%3];"
                         :: "r"(edst), "l"(ent + (size_t)ej * D_DIM),
                            "r"(400u), "r"(mb) : "memory");
        }
    }

    // ---- all lanes wait for every byte (phase 0) ----
    uint32_t done = 0;
    while (!done) {
        asm volatile(
            "{ .reg .pred p;\n\t"
            "  mbarrier.try_wait.parity.acquire.cta.shared::cta.b64 p, [%1], 0, 0x989680;\n\t"
            "  selp.b32 %0, 1, 0, p; }"
            : "=r"(done) : "r"(mb) : "memory");
    }

    // ---- entity average from smem (lanes 0..24, float4 each) ----
    float4 acc = make_float4(0.f, 0.f, 0.f, 0.f);
    if (lane < 25) {
        #pragma unroll
        for (int j = 0; j < T_SLOT; ++j) {
            if ((vmask >> j) & 1u) {
                const float4 r = reinterpret_cast<const float4*>(&entb[w][j][0])[lane];
                acc.x += r.x; acc.y += r.y; acc.z += r.z; acc.w += r.w;
            }
        }
        const float inv = 1.0f / (float)(cnt > 0 ? cnt : 1);
        acc.x *= inv; acc.y *= inv; acc.z *= inv; acc.w *= inv;
        reinterpret_cast<float4*>(out + (size_t)token * OUT_W + E_DIM)[lane] = acc;
    }

    // ---- token row leaves via bulk store (smem -> global) ----
    if (lane == 0) {
        const uint32_t tsrc = (uint32_t)__cvta_generic_to_shared(&tokb[w][0]);
        asm volatile("cp.async.bulk.global.shared::cta.bulk_group [%0], [%1], %2;"
                     :: "l"(out + (size_t)token * OUT_W),
                        "r"(tsrc), "r"(4096u) : "memory");
        asm volatile("cp.async.bulk.commit_group;" ::: "memory");
        asm volatile("cp.async.bulk.wait_group 0;" ::: "memory");
    }
}

extern "C" void kernel_launch(void* const* d_in, const int* in_sizes, int n_in,
                              void* d_out, int out_size)
{
    const int*   inputs  = (const int*)  d_in[0];
    const int*   triples = (const int*)  d_in[1];
    const int*   flags   = (const int*)  d_in[2];
    const float* emb     = (const float*)d_in[3];
    const float* ent     = (const float*)d_in[4];
    float*       out     = (float*)      d_out;

    fuse_triples_bulk_kernel<<<NTOK / WPB, 32 * WPB>>>(inputs, triples, flags,
                                                       emb, ent, out);
}

// round 7
// speedup vs baseline: 1.3433x; 1.2220x over previous
#include <cuda_runtime.h>
#include <cstdint>

#define NTOK   8192              // B*S
#define T_SLOT 16
#define E_DIM  1024
#define D_DIM  100
#define OUT_W  (E_DIM + D_DIM)   // 1124

__global__ __launch_bounds__(256)
void fuse_triples_cs_kernel(const int*   __restrict__ inputs,   // [NTOK]
                            const int*   __restrict__ triples,  // [NTOK,T,3]
                            const int*   __restrict__ flags,    // [NTOK,T]
                            const float* __restrict__ emb,      // [VOCAB,1024]
                            const float* __restrict__ ent,      // [ENT_VOCAB,100]
                            float*       __restrict__ out)      // [NTOK,1124]
{
    const int gwarp = (blockIdx.x * blockDim.x + threadIdx.x) >> 5;
    const int lane  = threadIdx.x & 31;
    const int token = gwarp;

    // ---- decode triple slots, one slot per lane (lanes 0..15) ----
    int e = -1;
    if (lane < T_SLOT) {
        const int f = flags[token * T_SLOT + lane];
        if (f == 1)      e = triples[(token * T_SLOT + lane) * 3 + 1]; // tail
        else if (f == 2) e = triples[(token * T_SLOT + lane) * 3 + 0]; // head
    }
    const unsigned vmask = __ballot_sync(0xffffffffu, e >= 0);
    const int cnt = __popc(vmask & 0xFFFFu);

    const int vrow = inputs[token];

    // ---- entity gather + average: lanes 0..24 own one float4 group ----
    // (issued first: random-latency path starts earliest)
    float4 acc = make_float4(0.f, 0.f, 0.f, 0.f);
    #pragma unroll
    for (int j = 0; j < T_SLOT; ++j) {
        const int ej = __shfl_sync(0xffffffffu, e, j);
        if (ej >= 0 && lane < 25) {
            const float4 r = reinterpret_cast<const float4*>(
                                 ent + (size_t)ej * D_DIM)[lane];
            acc.x += r.x; acc.y += r.y; acc.z += r.z; acc.w += r.w;
        }
    }
    if (lane < 25) {
        const float inv = 1.0f / (float)(cnt > 0 ? cnt : 1);
        acc.x *= inv; acc.y *= inv; acc.z *= inv; acc.w *= inv;
        // streaming store: do not let the output displace table lines in L2
        __stcs(reinterpret_cast<float4*>(out + (size_t)token * OUT_W + E_DIM) + lane,
               acc);
    }

    // ---- token embedding copy: 256 float4 by 32 lanes, 8 iters ----
    const float4* __restrict__ src =
        reinterpret_cast<const float4*>(emb + (size_t)vrow * E_DIM);
    float4* __restrict__ dst =
        reinterpret_cast<float4*>(out + (size_t)token * OUT_W);
    #pragma unroll
    for (int i = 0; i < 8; ++i) {
        const float4 v = src[lane + 32 * i];
        __stcs(dst + lane + 32 * i, v);     // streaming store, evict-first
    }
}

extern "C" void kernel_launch(void* const* d_in, const int* in_sizes, int n_in,
                              void* d_out, int out_size)
{
    const int*   inputs  = (const int*)  d_in[0];
    const int*   triples = (const int*)  d_in[1];
    const int*   flags   = (const int*)  d_in[2];
    const float* emb     = (const float*)d_in[3];
    const float* ent     = (const float*)d_in[4];
    float*       out     = (float*)      d_out;

    // one warp per token: 8192 warps = 1024 blocks * 8 warps
    fuse_triples_cs_kernel<<<NTOK / 8, 256>>>(inputs, triples, flags, emb, ent, out);
}